// round 6
// baseline (speedup 1.0000x reference)
#include <cuda_runtime.h>
#include <cstdint>

typedef unsigned long long u64;

#define Bn 64
#define Gn 200
#define QT 20
#define LH 204                 // h-stride of L (204 mod 32 = 12 -> conflict-free)
#define LQ (8 * LH)            // 1632 q-stride

// ---------------- scratch (static device arrays; no allocation) ----------------
__device__ float g_Q[Bn * Gn * 128];          // [b][g][h*16+k]
__device__ float g_K[Bn * Gn * 128];          // [b][g][h*16+k]
__device__ float g_V[Bn * Gn * 128];          // [b][g][h*16+v]

// ---------------- packed f32x2 helpers ----------------
__device__ __forceinline__ u64 fma2(u64 a, u64 b, u64 c) {
    u64 d; asm("fma.rn.f32x2 %0, %1, %2, %3;" : "=l"(d) : "l"(a), "l"(b), "l"(c)); return d;
}
__device__ __forceinline__ u64 pk(float lo, float hi) {
    u64 d; asm("mov.b64 %0, {%1, %2};" : "=l"(d) : "f"(lo), "f"(hi)); return d;
}
__device__ __forceinline__ float2 up(u64 a) {
    float2 r; asm("mov.b64 {%0, %1}, %2;" : "=f"(r.x), "=f"(r.y) : "l"(a)); return r;
}
__device__ __forceinline__ float hadd(u64 a) { float2 r = up(a); return r.x + r.y; }

// ================= kernel 1: QKV projections (register-tiled, o-split for 3 CTAs/SM) =================
#define SMEM1 ((8192 + 8320) * 4)

__global__ __launch_bounds__(256, 3) void proj_kernel(
    const float* __restrict__ h_em, const float* __restrict__ Wq,
    const float* __restrict__ Wk, const float* __restrict__ Wv)
{
    extern __shared__ float sm1[];
    float* Wsm = sm1;            // [d][o_local 64]
    float* xs  = sm1 + 8192;     // [d][gl] stride 65

    int t  = threadIdx.x;
    int tx = t & 15, ty = t >> 4;
    int g0 = blockIdx.x * 50;
    int b  = blockIdx.y;
    int w  = blockIdx.z;
    const float* W = (w == 0) ? Wq : (w == 1) ? Wk : Wv;
    float* outp    = (w == 0) ? g_Q : (w == 1) ? g_K : g_V;

    const float4* xsrc = (const float4*)(h_em + (size_t)(b * Gn + g0) * 128);
    for (int i4 = t; i4 < 1600; i4 += 256) {
        float4 v = xsrc[i4];
        int gl = i4 >> 5, d4 = (i4 & 31) * 4;
        xs[(d4 + 0) * 65 + gl] = v.x;
        xs[(d4 + 1) * 65 + gl] = v.y;
        xs[(d4 + 2) * 65 + gl] = v.z;
        xs[(d4 + 3) * 65 + gl] = v.w;
    }

    #pragma unroll 1
    for (int wh = 0; wh < 2; wh++) {
        if (wh) __syncthreads();
        for (int idx = t; idx < 8192; idx += 256) {
            int hl = idx >> 11, d = (idx >> 4) & 127, k = idx & 15;
            Wsm[d * 64 + hl * 16 + k] = W[(wh * 4 + hl) * 2048 + d * 16 + k];
        }
        __syncthreads();

        u64 acc[4][2];
        #pragma unroll
        for (int i = 0; i < 4; i++) { acc[i][0] = 0ull; acc[i][1] = 0ull; }

        const u64* Wp = (const u64*)Wsm;
        #pragma unroll 4
        for (int d = 0; d < 128; d++) {
            u64 wv0 = Wp[d * 32 + tx];
            u64 wv1 = Wp[d * 32 + tx + 16];
            #pragma unroll
            for (int i = 0; i < 4; i++) {
                float x = xs[d * 65 + i * 16 + ty];
                u64 xv = pk(x, x);
                acc[i][0] = fma2(xv, wv0, acc[i][0]);
                acc[i][1] = fma2(xv, wv1, acc[i][1]);
            }
        }
        #pragma unroll
        for (int i = 0; i < 4; i++) {
            int gl = i * 16 + ty;
            if (gl < 50) {
                float* op = outp + (size_t)(b * Gn + g0 + gl) * 128 + wh * 64 + tx * 2;
                *(u64*)op        = acc[i][0];
                *(u64*)(op + 32) = acc[i][1];
            }
        }
    }
}

// ================= kernel 2: fused qk + route + MLP + softmax + AV + Wout =================
// grid (10, 64); 512 threads; smem 208576 B; 1 CTA/SM, 16 warps, up to 128 regs.
#define SMEM2 208576

__global__ __launch_bounds__(512, 1) void main_kernel(
    const float* __restrict__ route, const float* __restrict__ W1,
    const float* __restrict__ b1, const float* __restrict__ W2,
    const float* __restrict__ b2, const float* __restrict__ Wo,
    float* __restrict__ out, float* __restrict__ out_route)
{
    extern __shared__ char smraw[];
    float* L      = (float*)smraw;           // 32640 f : [q][h][g] strides LQ/LH
    float* Qsm    = L + 32640;               // 2560 f  : [q][chunk-swizzled 128]
    float* hp     = Qsm + 2560;              // 10752 f : [s(4)][hv][21]
    u64*   headsd = (u64*)(hp + 10752);      // 2560 u64: [q][hv] dup pairs
    u64*   W1d    = headsd + 2560;           // 384
    u64*   W2d    = W1d + 384;               // 128
    u64*   b1d    = W2d + 128;               // 16
    u64*   b2d    = b1d + 16;                // 8

    int t  = threadIdx.x;
    int b  = blockIdx.y;
    int q0 = blockIdx.x * QT;

    // ---- phase 0: stage Q (chunk-permuted), dup weight tables ----
    const float4* Qs = (const float4*)(g_Q + (size_t)(b * Gn + q0) * 128);
    for (int i4 = t; i4 < 640; i4 += 512) {
        float4 v = Qs[i4];
        int q = i4 >> 5, rem = i4 & 31, h = rem >> 2, c = rem & 3;
        int chunk = h * 4 + ((c + (h >> 1)) & 3);
        *(float4*)(Qsm + q * 128 + chunk * 4) = v;
    }
    if (t < 384) W1d[t] = pk(W1[t], W1[t]);
    if (t >= 384 && t < 512) { int i = t - 384; W2d[i] = pk(W2[i], W2[i]); }
    if (t < 16)  { b1d[t] = pk(b1[t], b1[t]); }
    if (t >= 16 && t < 24) { int i = t - 16; b2d[i] = pk(b2[i], b2[i]); }
    __syncthreads();

    // ---- phase 1a: raw qk -> L.  item = (g-pair, h); K pair resident, amortized over 20 q ----
    for (int u = t; u < 800; u += 512) {
        int gp = u >> 3, h = u & 7, g = gp * 2;
        const ulonglong2* K0 = (const ulonglong2*)(g_K + (size_t)(b * Gn + g) * 128 + h * 16);
        const ulonglong2* K1 = (const ulonglong2*)(g_K + (size_t)(b * Gn + g + 1) * 128 + h * 16);
        ulonglong2 k0[4], k1[4];
        #pragma unroll
        for (int c = 0; c < 4; c++) { k0[c] = K0[c]; k1[c] = K1[c]; }
        int h2 = h >> 1;
        float* Ld = L + h * LH + g;
        #pragma unroll 4
        for (int q = 0; q < QT; q++) {
            const float* Qr = Qsm + q * 128;
            u64 a0 = 0ull, a1 = 0ull;
            #pragma unroll
            for (int c = 0; c < 4; c++) {
                int p = h * 4 + ((c + h2) & 3);
                ulonglong2 qc = *(const ulonglong2*)(Qr + p * 4);
                a0 = fma2(k0[c].x, qc.x, a0); a0 = fma2(k0[c].y, qc.y, a0);
                a1 = fma2(k1[c].x, qc.x, a1); a1 = fma2(k1[c].y, qc.y, a1);
            }
            *(u64*)(Ld + q * LQ) = pk(hadd(a0), hadd(a1));
        }
    }
    __syncthreads();

    // ---- phase 1b: one g-QUAD per thread: 2 pair-lanes share every weight load ----
    const ulonglong2* W1p = (const ulonglong2*)W1d;
    const ulonglong2* W2p = (const ulonglong2*)W2d;
    for (int u = t; u < 1000; u += 512) {
        int q  = u / 50;
        int gq = u - q * 50;
        int g  = gq * 4;
        u64 hidA[16], hidB[16];
        #pragma unroll
        for (int j = 0; j < 16; j++) { hidA[j] = b1d[j]; hidB[j] = b1d[j]; }
        float* Lqg = L + q * LQ + g;
        #pragma unroll
        for (int h = 0; h < 8; h += 2) {
            ulonglong2 x0 = *(const ulonglong2*)(Lqg + h * LH);         // (g,g+1),(g+2,g+3)
            ulonglong2 x1 = *(const ulonglong2*)(Lqg + (h + 1) * LH);
            #pragma unroll
            for (int j = 0; j < 16; j++) {
                ulonglong2 w = W1p[j * 12 + (h >> 1)];
                hidA[j] = fma2(x0.x, w.x, hidA[j]);
                hidB[j] = fma2(x0.y, w.x, hidB[j]);
                hidA[j] = fma2(x1.x, w.y, hidA[j]);
                hidB[j] = fma2(x1.y, w.y, hidB[j]);
            }
        }
        size_t ridx = (size_t)(b * Gn + q0 + q) * Gn + g;
        const float* rp = route + ridx;
        float* wp = out_route ? (out_route + ridx) : (float*)0;
        #pragma unroll
        for (int r0 = 0; r0 < 16; r0 += 2) {
            float4 ra = __ldcs((const float4*)(rp + (size_t)(r0 + 0) * 2560000));
            float4 rb = __ldcs((const float4*)(rp + (size_t)(r0 + 1) * 2560000));
            if (wp) {
                __stcs((float4*)(wp + (size_t)(r0 + 0) * 2560000), ra);
                __stcs((float4*)(wp + (size_t)(r0 + 1) * 2560000), rb);
            }
            u64 ra0 = pk(ra.x, ra.y), ra1 = pk(ra.z, ra.w);
            u64 rb0 = pk(rb.x, rb.y), rb1 = pk(rb.z, rb.w);
            #pragma unroll
            for (int j = 0; j < 16; j++) {
                ulonglong2 w = W1p[j * 12 + 4 + (r0 >> 1)];
                hidA[j] = fma2(ra0, w.x, hidA[j]);
                hidB[j] = fma2(ra1, w.x, hidB[j]);
                hidA[j] = fma2(rb0, w.y, hidA[j]);
                hidB[j] = fma2(rb1, w.y, hidB[j]);
            }
        }
        #pragma unroll
        for (int j = 0; j < 16; j++) {
            float2 va = up(hidA[j]);
            hidA[j] = pk(fmaxf(va.x, 0.f), fmaxf(va.y, 0.f));
            float2 vb = up(hidB[j]);
            hidB[j] = pk(fmaxf(vb.x, 0.f), fmaxf(vb.y, 0.f));
        }
        #pragma unroll
        for (int h = 0; h < 8; h++) {
            u64 aA = b2d[h], aB = b2d[h];
            #pragma unroll
            for (int j = 0; j < 16; j += 2) {
                ulonglong2 w = W2p[(h * 16 + j) >> 1];
                aA = fma2(hidA[j], w.x, aA);
                aB = fma2(hidB[j], w.x, aB);
                aA = fma2(hidA[j + 1], w.y, aA);
                aB = fma2(hidB[j + 1], w.y, aB);
            }
            ulonglong2 st; st.x = aA; st.y = aB;
            *(ulonglong2*)(Lqg + h * LH) = st;
        }
    }
    __syncthreads();

    // ---- phase 2: softmax over g, one warp per (q,h) row; 160 rows / 16 warps ----
    {
        int warp = t >> 5, lane = t & 31;
        for (int row = warp; row < 160; row += 16) {
            float* Lr = L + (row >> 3) * LQ + (row & 7) * LH;
            float m = -1e30f;
            for (int i = lane; i < 200; i += 32) m = fmaxf(m, Lr[i]);
            #pragma unroll
            for (int o = 16; o > 0; o >>= 1) m = fmaxf(m, __shfl_xor_sync(0xffffffffu, m, o));
            float s = 0.f;
            for (int i = lane; i < 200; i += 32) { float e = __expf(Lr[i] - m); Lr[i] = e; s += e; }
            #pragma unroll
            for (int o = 16; o > 0; o >>= 1) s += __shfl_xor_sync(0xffffffffu, s, o);
            float inv = 1.f / s;
            for (int i = lane; i < 200; i += 32) Lr[i] *= inv;
        }
    }
    __syncthreads();

    // ---- phase 3: heads[q][hv] = sum_g p[q][h][g] * V[g][hv]; g-quads, slices {52,52,48,48} ----
    {
        int s = t >> 7, hv = t & 127, h = hv >> 4;
        int base = s * 48 + ((s < 2) ? s * 4 : 8);   // 0, 52, 104, 152
        int len  = (s < 2) ? 52 : 48;
        const float* Vp = g_V + (size_t)(b * Gn + base) * 128 + hv;
        const float* Lh = L + h * LH + base;
        u64 acc[QT];
        #pragma unroll
        for (int q = 0; q < QT; q++) acc[q] = 0ull;
        for (int i = 0; i < len; i += 4) {
            float v0 = Vp[(i + 0) * 128], v1 = Vp[(i + 1) * 128];
            float v2 = Vp[(i + 2) * 128], v3 = Vp[(i + 3) * 128];
            u64 va = pk(v0, v1), vb = pk(v2, v3);
            #pragma unroll
            for (int q = 0; q < QT; q++) {
                ulonglong2 p = *(const ulonglong2*)(Lh + q * LQ + i);
                acc[q] = fma2(p.x, va, acc[q]);
                acc[q] = fma2(p.y, vb, acc[q]);
            }
        }
        float* hpd = hp + (s * 128 + hv) * 21;
        #pragma unroll
        for (int q = 0; q < QT; q++) hpd[q] = hadd(acc[q]);
    }
    __syncthreads();
    if (t < 128) {
        #pragma unroll
        for (int q = 0; q < QT; q++) {
            float v = hp[t * 21 + q] + hp[(128 + t) * 21 + q]
                    + hp[(256 + t) * 21 + q] + hp[(384 + t) * 21 + q];
            headsd[q * 128 + t] = pk(v, v);
        }
    }
    __syncthreads();

    // ---- epilogue: Wo-reuse. 128 threads: (hv-half, e-pair), all 20 q per Wo load ----
    u64* scratch = (u64*)L;     // L is dead; need 128*20 u64 = 20 KB
    if (t < 128) {
        int half = t >> 6, ep = t & 63;
        const u64* Wop = (const u64*)Wo + ep;        // row stride 64 u64
        u64 acc[QT];
        #pragma unroll
        for (int q = 0; q < QT; q++) acc[q] = 0ull;
        int hv0 = half * 64;
        for (int hv = hv0; hv < hv0 + 64; hv += 2) {
            u64 w0 = Wop[hv * 64];
            u64 w1 = Wop[(hv + 1) * 64];
            #pragma unroll
            for (int q = 0; q < QT; q++) {
                ulonglong2 hh = *(const ulonglong2*)(headsd + q * 128 + hv);
                acc[q] = fma2(hh.x, w0, acc[q]);
                acc[q] = fma2(hh.y, w1, acc[q]);
            }
        }
        #pragma unroll
        for (int q = 0; q < QT; q++) scratch[t * QT + q] = acc[q];
    }
    __syncthreads();
    if (t < 64) {
        #pragma unroll
        for (int q = 0; q < QT; q++) {
            float2 a = up(scratch[t * QT + q]);
            float2 c = up(scratch[(64 + t) * QT + q]);
            float2 r; r.x = a.x + c.x; r.y = a.y + c.y;
            *(float2*)(out + (size_t)(b * Gn + q0 + q) * 128 + t * 2) = r;
        }
    }
}

extern "C" void kernel_launch(void* const* d_in, const int* in_sizes, int n_in,
                              void* d_out, int out_size) {
    const float* h_em  = (const float*)d_in[0];
    const float* route = (const float*)d_in[1];
    const float* Wq    = (const float*)d_in[2];
    const float* Wk    = (const float*)d_in[3];
    const float* Wv    = (const float*)d_in[4];
    const float* W1    = (const float*)d_in[5];
    const float* b1    = (const float*)d_in[6];
    const float* W2    = (const float*)d_in[7];
    const float* b2    = (const float*)d_in[8];
    const float* Wo    = (const float*)d_in[9];
    float* out = (float*)d_out;

    float* out_route = nullptr;
    if (out_size >= 1638400 + 40960000) out_route = out + 1638400;

    static bool attr_done = false;
    if (!attr_done) {
        cudaFuncSetAttribute(proj_kernel, cudaFuncAttributeMaxDynamicSharedMemorySize, SMEM1);
        cudaFuncSetAttribute(main_kernel, cudaFuncAttributeMaxDynamicSharedMemorySize, SMEM2);
        attr_done = true;
    }

    dim3 grid1(4, Bn, 3);
    proj_kernel<<<grid1, 256, SMEM1>>>(h_em, Wq, Wk, Wv);
    dim3 grid2(Gn / QT, Bn);
    main_kernel<<<grid2, 512, SMEM2>>>(route, W1, b1, W2, b2, Wo, out, out_route);
}